// round 7
// baseline (speedup 1.0000x reference)
#include <cuda_runtime.h>
#include <math.h>
#include <stdint.h>

#define DM 512
#define NH 8
#define HD 64
#define NB 4
#define SQ 2048
#define M_ROWS (NB*SQ)   // 8192
#define BH (NB*NH)       // 32

// Scratch (no allocation allowed): q,k,v,ctx in [B,H,S,Dh] layout
__device__ float g_q[(size_t)BH*SQ*HD];
__device__ float g_k[(size_t)BH*SQ*HD];
__device__ float g_v[(size_t)BH*SQ*HD];
__device__ float g_ctx[(size_t)BH*SQ*HD];

// ---------------------------------------------------------------------------
// tf32x3: split fp32 into tf32 hi + lo. Splits happen in the LOADER phase
// (once per element), not in the MMA loop.
// ---------------------------------------------------------------------------
__device__ __forceinline__ uint32_t f2tf32(float f){
    uint32_t r;
    asm("cvt.rna.tf32.f32 %0, %1;" : "=r"(r) : "f"(f));
    return r;
}
__device__ __forceinline__ void split_tf32(float f, uint32_t& h, uint32_t& l){
    uint32_t hb = f2tf32(f);
    h = hb;
    l = f2tf32(f - __uint_as_float(hb));
}
__device__ __forceinline__ void mma8(float* c, const uint32_t* a, const uint32_t* b){
    asm volatile("mma.sync.aligned.m16n8k8.row.col.f32.tf32.tf32.f32 "
        "{%0,%1,%2,%3}, {%4,%5,%6,%7}, {%8,%9}, {%0,%1,%2,%3};\n"
        : "+f"(c[0]), "+f"(c[1]), "+f"(c[2]), "+f"(c[3])
        : "r"(a[0]), "r"(a[1]), "r"(a[2]), "r"(a[3]), "r"(b[0]), "r"(b[1]));
}

// Shared tile types: pre-split hi/lo, k-major, skewed stride (136/72 ≡ 8 mod 32)
struct SmemTiles {
    uint32_t Ah[16][136];
    uint32_t Al[16][136];
    uint32_t Bh[16][72];
    uint32_t Bl[16][72];
};

// 128x64x16 chunk: 8 warps as 4(M)x2(N), warp tile 32x32. Pure LDS + MMA.
__device__ __forceinline__ void mma_chunk(const SmemTiles& t, float acc[2][4][4],
                                          int wm, int wn, int g, int tg)
{
    #pragma unroll
    for (int s = 0; s < 2; s++){
        const int kb = 8*s;
        uint32_t ah[2][4], al[2][4], bh[4][2], bl[4][2];
        #pragma unroll
        for (int am = 0; am < 2; am++){
            const int mb = wm*32 + am*16 + g;
            ah[am][0]=t.Ah[kb+tg  ][mb  ]; al[am][0]=t.Al[kb+tg  ][mb  ];
            ah[am][1]=t.Ah[kb+tg  ][mb+8]; al[am][1]=t.Al[kb+tg  ][mb+8];
            ah[am][2]=t.Ah[kb+tg+4][mb  ]; al[am][2]=t.Al[kb+tg+4][mb  ];
            ah[am][3]=t.Ah[kb+tg+4][mb+8]; al[am][3]=t.Al[kb+tg+4][mb+8];
        }
        #pragma unroll
        for (int bn = 0; bn < 4; bn++){
            const int nb = wn*32 + bn*8 + g;
            bh[bn][0]=t.Bh[kb+tg  ][nb]; bl[bn][0]=t.Bl[kb+tg  ][nb];
            bh[bn][1]=t.Bh[kb+tg+4][nb]; bl[bn][1]=t.Bl[kb+tg+4][nb];
        }
        #pragma unroll
        for (int am = 0; am < 2; am++)
            #pragma unroll
            for (int bn = 0; bn < 4; bn++){
                mma8(acc[am][bn], ah[am], bh[bn]);   // hi*hi
                mma8(acc[am][bn], ah[am], bl[bn]);   // hi*lo
                mma8(acc[am][bn], al[am], bh[bn]);   // lo*hi
            }
    }
}

// Loader helper: split a float4 of k-consecutive values into hi/lo smem columns
__device__ __forceinline__ void put4A(SmemTiles& t, int k4, int mm, float4 v){
    split_tf32(v.x, t.Ah[k4+0][mm], t.Al[k4+0][mm]);
    split_tf32(v.y, t.Ah[k4+1][mm], t.Al[k4+1][mm]);
    split_tf32(v.z, t.Ah[k4+2][mm], t.Al[k4+2][mm]);
    split_tf32(v.w, t.Ah[k4+3][mm], t.Al[k4+3][mm]);
}
__device__ __forceinline__ void put4B(SmemTiles& t, int k4, int nn, float4 v){
    split_tf32(v.x, t.Bh[k4+0][nn], t.Bl[k4+0][nn]);
    split_tf32(v.y, t.Bh[k4+1][nn], t.Bl[k4+1][nn]);
    split_tf32(v.z, t.Bh[k4+2][nn], t.Bl[k4+2][nn]);
    split_tf32(v.w, t.Bh[k4+3][nn], t.Bl[k4+3][nn]);
}

// ---------------------------------------------------------------------------
// Projection: out = X[8192,512] @ W^T + b, scattered to [B,H,S,Dh]
// ---------------------------------------------------------------------------
__global__ void __launch_bounds__(256, 3)
proj_kernel(const float* __restrict__ X, const float* __restrict__ W,
            const float* __restrict__ bias, int which)
{
    __shared__ SmemTiles t;
    const int tid = threadIdx.x;
    const int lane = tid & 31, warp = tid >> 5;
    const int wm = warp & 3, wn = warp >> 2;
    const int g = lane >> 2, tg = lane & 3;
    const int m0 = blockIdx.y * 128, n0 = blockIdx.x * 64;
    float* __restrict__ out = (which == 0) ? g_q : (which == 1) ? g_k : g_v;

    float acc[2][4][4] = {};
    for (int k0 = 0; k0 < DM; k0 += 16){
        #pragma unroll
        for (int i = 0; i < 2; i++){
            int idx = tid + 256*i;
            int mm = idx & 127, q4 = idx >> 7;
            put4A(t, q4*4, mm, *(const float4*)&X[(size_t)(m0+mm)*DM + k0 + q4*4]);
        }
        {
            int nn = tid & 63, q4 = tid >> 6;
            put4B(t, q4*4, nn, *(const float4*)&W[(size_t)(n0+nn)*DM + k0 + q4*4]);
        }
        __syncthreads();
        mma_chunk(t, acc, wm, wn, g, tg);
        __syncthreads();
    }
    #pragma unroll
    for (int am = 0; am < 2; am++)
      #pragma unroll
      for (int bn = 0; bn < 4; bn++)
        #pragma unroll
        for (int c = 0; c < 4; c++){
            int m = m0 + wm*32 + am*16 + g + ((c>>1)<<3);
            int n = n0 + wn*32 + bn*8 + tg*2 + (c&1);
            int b_ = m >> 11, s = m & (SQ-1);
            int h = n >> 6, dh = n & 63;
            out[(size_t)((b_*NH + h)*SQ + s)*HD + dh] = acc[am][bn][c] + bias[n];
        }
}

// ---------------------------------------------------------------------------
// Causal QK^T: 128x64 tiles; upper tiles zero-filled; diagonal band masked.
// ---------------------------------------------------------------------------
__global__ void __launch_bounds__(256, 3)
qk_kernel(float* __restrict__ attn)
{
    const int bh = blockIdx.z;
    const int m0 = blockIdx.y * 128, n0 = blockIdx.x * 64;
    float* __restrict__ out = attn + (size_t)bh * SQ * SQ;
    const int tid = threadIdx.x;

    if (n0 >= m0 + 128){   // tile entirely above diagonal
        #pragma unroll
        for (int i = 0; i < 8; i++){
            int idx = tid + 256*i;
            int r = idx >> 4, cq = idx & 15;
            *(float4*)&out[(size_t)(m0+r)*SQ + n0 + cq*4] = make_float4(0.f,0.f,0.f,0.f);
        }
        return;
    }

    const float* __restrict__ q = g_q + (size_t)bh * SQ * HD;
    const float* __restrict__ k = g_k + (size_t)bh * SQ * HD;
    __shared__ SmemTiles t;
    const int lane = tid & 31, warp = tid >> 5;
    const int wm = warp & 3, wn = warp >> 2;
    const int g = lane >> 2, tg = lane & 3;
    float acc[2][4][4] = {};

    for (int k0 = 0; k0 < HD; k0 += 16){
        #pragma unroll
        for (int i = 0; i < 2; i++){
            int idx = tid + 256*i;
            int mm = idx & 127, q4 = idx >> 7;
            put4A(t, q4*4, mm, *(const float4*)&q[(size_t)(m0+mm)*HD + k0 + q4*4]);
        }
        {
            int nn = tid & 63, q4 = tid >> 6;
            put4B(t, q4*4, nn, *(const float4*)&k[(size_t)(n0+nn)*HD + k0 + q4*4]);
        }
        __syncthreads();
        mma_chunk(t, acc, wm, wn, g, tg);
        __syncthreads();
    }
    #pragma unroll
    for (int am = 0; am < 2; am++)
      #pragma unroll
      for (int bn = 0; bn < 4; bn++)
        #pragma unroll
        for (int c = 0; c < 4; c++){
            int gi = m0 + wm*32 + am*16 + g + ((c>>1)<<3);
            int gj = n0 + wn*32 + bn*8 + tg*2 + (c&1);
            out[(size_t)gi*SQ + gj] = (gj <= gi) ? acc[am][bn][c]*0.125f : 0.f;
        }
}

// ---------------------------------------------------------------------------
// Row softmax over causal prefix: whole row in registers — 1 read, 1 write.
// ---------------------------------------------------------------------------
__global__ void softmax_kernel(float* __restrict__ attn)
{
    const int row = blockIdx.x;          // bh*SQ + i
    const int i = row & (SQ - 1);
    float* __restrict__ p = attn + (size_t)row * SQ;
    const int n = i + 1;
    const int tid = threadIdx.x;
    __shared__ float red[256];

    float v[8];
    float mx = -1e30f;
    #pragma unroll
    for (int t = 0; t < 8; t++){
        int j = tid + 256*t;
        if (j < n){ v[t] = p[j]; mx = fmaxf(mx, v[t]); }
    }
    red[tid] = mx; __syncthreads();
    #pragma unroll
    for (int s = 128; s > 0; s >>= 1){
        if (tid < s) red[tid] = fmaxf(red[tid], red[tid+s]);
        __syncthreads();
    }
    mx = red[0]; __syncthreads();

    float sum = 0.f;
    #pragma unroll
    for (int t = 0; t < 8; t++){
        int j = tid + 256*t;
        if (j < n){ v[t] = __expf(v[t] - mx); sum += v[t]; }
    }
    red[tid] = sum; __syncthreads();
    #pragma unroll
    for (int s = 128; s > 0; s >>= 1){
        if (tid < s) red[tid] += red[tid+s];
        __syncthreads();
    }
    float inv = 1.f / red[0];
    #pragma unroll
    for (int t = 0; t < 8; t++){
        int j = tid + 256*t;
        if (j < n) p[j] = v[t] * inv;    // cols > i stay exactly 0
    }
}

// ---------------------------------------------------------------------------
// AV: ctx[128-row tile] = P[128, 0..m0+128) @ V; K truncated at diagonal.
// ---------------------------------------------------------------------------
__global__ void __launch_bounds__(256, 3)
av_kernel(const float* __restrict__ attn)
{
    const int bh = blockIdx.z;
    const int m0 = blockIdx.y * 128;
    const float* __restrict__ A  = attn + (size_t)bh*SQ*SQ;
    const float* __restrict__ Vh = g_v  + (size_t)bh*SQ*HD;
    float* __restrict__ C = g_ctx + (size_t)bh*SQ*HD;
    __shared__ SmemTiles t;
    const int tid = threadIdx.x;
    const int lane = tid & 31, warp = tid >> 5;
    const int wm = warp & 3, wn = warp >> 2;
    const int g = lane >> 2, tg = lane & 3;
    float acc[2][4][4] = {};

    const int kend = m0 + 128;          // causal truncation
    for (int k0 = 0; k0 < kend; k0 += 16){
        #pragma unroll
        for (int i = 0; i < 2; i++){
            int idx = tid + 256*i;
            int mm = idx & 127, q4 = idx >> 7;
            put4A(t, q4*4, mm, *(const float4*)&A[(size_t)(m0+mm)*SQ + k0 + q4*4]);
        }
        {
            int kk = tid >> 4, nq = tid & 15;     // V: n-major per k row
            float4 v = *(const float4*)&Vh[(size_t)(k0+kk)*HD + nq*4];
            split_tf32(v.x, t.Bh[kk][nq*4+0], t.Bl[kk][nq*4+0]);
            split_tf32(v.y, t.Bh[kk][nq*4+1], t.Bl[kk][nq*4+1]);
            split_tf32(v.z, t.Bh[kk][nq*4+2], t.Bl[kk][nq*4+2]);
            split_tf32(v.w, t.Bh[kk][nq*4+3], t.Bl[kk][nq*4+3]);
        }
        __syncthreads();
        mma_chunk(t, acc, wm, wn, g, tg);
        __syncthreads();
    }
    #pragma unroll
    for (int am = 0; am < 2; am++)
      #pragma unroll
      for (int bn = 0; bn < 4; bn++)
        #pragma unroll
        for (int c = 0; c < 4; c++){
            int m = m0 + wm*32 + am*16 + g + ((c>>1)<<3);
            int ncol = wn*32 + bn*8 + tg*2 + (c&1);
            C[(size_t)m*HD + ncol] = acc[am][bn][c];
        }
}

// ---------------------------------------------------------------------------
// Output projection: x = ctx(gathered as [8192,512]) @ w_o^T + b_o
// ---------------------------------------------------------------------------
__global__ void __launch_bounds__(256, 3)
outproj_kernel(const float* __restrict__ W, const float* __restrict__ bias,
               float* __restrict__ outp)
{
    __shared__ SmemTiles t;
    const int tid = threadIdx.x;
    const int lane = tid & 31, warp = tid >> 5;
    const int wm = warp & 3, wn = warp >> 2;
    const int g = lane >> 2, tg = lane & 3;
    const int m0 = blockIdx.y * 128, n0 = blockIdx.x * 64;
    float acc[2][4][4] = {};

    for (int k0 = 0; k0 < DM; k0 += 16){
        #pragma unroll
        for (int i = 0; i < 2; i++){
            int idx = tid + 256*i;
            int mm = idx & 127, q4 = idx >> 7;
            int m = m0 + mm;
            int b_ = m >> 11, s = m & (SQ-1);
            int kk = k0 + q4*4;
            int h = kk >> 6, dh = kk & 63;      // float4 stays inside one head
            put4A(t, q4*4, mm,
                  *(const float4*)&g_ctx[(size_t)((b_*NH + h)*SQ + s)*HD + dh]);
        }
        {
            int nn = tid & 63, q4 = tid >> 6;
            put4B(t, q4*4, nn, *(const float4*)&W[(size_t)(n0+nn)*DM + k0 + q4*4]);
        }
        __syncthreads();
        mma_chunk(t, acc, wm, wn, g, tg);
        __syncthreads();
    }
    #pragma unroll
    for (int am = 0; am < 2; am++)
      #pragma unroll
      for (int bn = 0; bn < 4; bn++)
        #pragma unroll
        for (int c = 0; c < 4; c++){
            int m = m0 + wm*32 + am*16 + g + ((c>>1)<<3);
            int n = n0 + wn*32 + bn*8 + tg*2 + (c&1);
            outp[(size_t)m*DM + n] = acc[am][bn][c] + bias[n];
        }
}

// ---------------------------------------------------------------------------
extern "C" void kernel_launch(void* const* d_in, const int* in_sizes, int n_in,
                              void* d_out, int out_size)
{
    const float* Q   = (const float*)d_in[0];
    const float* K   = (const float*)d_in[1];
    const float* V   = (const float*)d_in[2];
    // d_in[3] is the causal mask — computed analytically instead.
    const float* w_q = (const float*)d_in[4];
    const float* b_q = (const float*)d_in[5];
    const float* w_k = (const float*)d_in[6];
    const float* b_k = (const float*)d_in[7];
    const float* w_v = (const float*)d_in[8];
    const float* b_v = (const float*)d_in[9];
    const float* w_o = (const float*)d_in[10];
    const float* b_o = (const float*)d_in[11];

    float* out_x = (float*)d_out;
    float* attn  = (float*)d_out + (size_t)M_ROWS * DM;

    dim3 blk(256);
    proj_kernel<<<dim3(DM/64, M_ROWS/128), blk>>>(Q, w_q, b_q, 0);
    proj_kernel<<<dim3(DM/64, M_ROWS/128), blk>>>(K, w_k, b_k, 1);
    proj_kernel<<<dim3(DM/64, M_ROWS/128), blk>>>(V, w_v, b_v, 2);

    qk_kernel<<<dim3(SQ/64, SQ/128, BH), blk>>>(attn);
    softmax_kernel<<<BH*SQ, 256>>>(attn);
    av_kernel<<<dim3(1, SQ/128, BH), blk>>>(attn);
    outproj_kernel<<<dim3(DM/64, M_ROWS/128), blk>>>(w_o, b_o, out_x);
}